// round 17
// baseline (speedup 1.0000x reference)
#include <cuda_runtime.h>
#include <cuda_fp16.h>
#include <math.h>

#define WW 512
#define HH 512
#define NIMG 8
#define HWSZ (HH * WW)
#define NPLANES 16            // 2 streams (p, target) x 8 samples
#define TOTALSZ (NPLANES * HWSZ)
#define NITER 50

#define STRIPS 5              // 5 strips x 120 output cols (lanes 1..30 of 4-col lanes)
#define CHUNK_ROWS 16
#define CHUNKS 32             // 512 / 16
#define WARPS_TOTAL (STRIPS * CHUNKS * NPLANES)   // 2560

#define IT2_BLOCK 128
#define IT2_GRID (WARPS_TOTAL / (IT2_BLOCK / 32))      // 640

// Static scratch (no allocations allowed in kernel_launch)
__device__ __half g_imgA[TOTALSZ];     // ping (fp16)
__device__ __half g_imgB[TOTALSZ];     // pong (fp16)
__device__ __half g_skel[TOTALSZ];     // skeleton accumulators (fp16)
__device__ double g_sums[NIMG][7];     // per-sample reduction accumulators

// ---------------------------------------------------------------------------
// fp16x4 helpers: one lane owns 4 adjacent columns as {lo=(c0,c1), hi=(c2,c3)}
// ---------------------------------------------------------------------------
struct __align__(8) H4 { __half2 lo, hi; };

__device__ __forceinline__ __half h_inf()  { return __ushort_as_half((unsigned short)0x7C00); }
__device__ __forceinline__ __half h_ninf() { return __ushort_as_half((unsigned short)0xFC00); }
__device__ __forceinline__ H4 h4fill(__half v) { __half2 p = __half2half2(v); H4 r; r.lo = p; r.hi = p; return r; }
__device__ __forceinline__ H4 h4_inf()  { return h4fill(h_inf()); }
__device__ __forceinline__ H4 h4_ninf() { return h4fill(h_ninf()); }
__device__ __forceinline__ H4 h4_zero() { return h4fill(__ushort_as_half(0)); }

__device__ __forceinline__ H4 min_h(H4 a, H4 b) { H4 r; r.lo = __hmin2(a.lo, b.lo); r.hi = __hmin2(a.hi, b.hi); return r; }
__device__ __forceinline__ H4 max_h(H4 a, H4 b) { H4 r; r.lo = __hmax2(a.lo, b.lo); r.hi = __hmax2(a.hi, b.hi); return r; }

// horizontal combine with EXPLICIT edge values (no shuffle inside)
__device__ __forceinline__ H4 comb_minh(H4 v, __half L, __half R, int lane) {
    if (lane == 0)  L = h_inf();
    if (lane == 31) R = h_inf();
    __half2 La = __halves2half2(L, __low2half(v.lo));
    __half2 bc = __halves2half2(__high2half(v.lo), __low2half(v.hi));
    __half2 dR = __halves2half2(__high2half(v.hi), R);
    H4 o;
    o.lo = __hmin2(__hmin2(La, v.lo), bc);
    o.hi = __hmin2(__hmin2(bc, v.hi), dR);
    return o;
}
__device__ __forceinline__ H4 comb_maxh(H4 v, __half L, __half R, int lane) {
    if (lane == 0)  L = h_ninf();
    if (lane == 31) R = h_ninf();
    __half2 La = __halves2half2(L, __low2half(v.lo));
    __half2 bc = __halves2half2(__high2half(v.lo), __low2half(v.hi));
    __half2 dR = __halves2half2(__high2half(v.hi), R);
    H4 o;
    o.lo = __hmax2(__hmax2(La, v.lo), bc);
    o.hi = __hmax2(__hmax2(bc, v.hi), dR);
    return o;
}
// same-step shuffle variant
__device__ __forceinline__ H4 hmax3h(H4 v, int lane) {
    __half2 fl = __shfl_up_sync(0xffffffffu, v.hi, 1);
    __half2 fr = __shfl_down_sync(0xffffffffu, v.lo, 1);
    return comb_maxh(v, __high2half(fl), __low2half(fr), lane);
}
__device__ __forceinline__ void edges_of(H4 v, __half& L, __half& R) {
    __half2 s1 = __shfl_up_sync(0xffffffffu, v.hi, 1);
    __half2 s2 = __shfl_down_sync(0xffffffffu, v.lo, 1);
    L = __high2half(s1); R = __low2half(s2);
}
__device__ __forceinline__ H4 relu_subh(H4 a, H4 b) {
    __half2 z = __half2half2(__ushort_as_half(0));
    H4 r;
    r.lo = __hmax2(__hsub2(a.lo, b.lo), z);
    r.hi = __hmax2(__hsub2(a.hi, b.hi), z);
    return r;
}
__device__ __forceinline__ H4 selneg(H4 v, bool ok) { return ok ? v : h4_ninf(); }
// s += relu(d - s*d)
__device__ __forceinline__ void skel_updh(H4& s, H4 d) {
    s.lo = __hadd2(s.lo, __hfma2_relu(__hneg2(s.lo), d.lo, d.lo));
    s.hi = __hadd2(s.hi, __hfma2_relu(__hneg2(s.hi), d.hi, d.hi));
}

// ---------------------------------------------------------------------------
// Init: imgA[stream0]=half(sigmoid(output)), imgA[stream1]=half(target)
// ---------------------------------------------------------------------------
__global__ void k_init(const float4* __restrict__ out, const float4* __restrict__ tgt) {
    int i = blockIdx.x * blockDim.x + threadIdx.x;
    int stride = gridDim.x * blockDim.x;
    H4* ga = (H4*)g_imgA;
    H4* gb = (H4*)(g_imgA + NIMG * HWSZ);
    const int n4 = NIMG * HWSZ / 4;
    for (; i < n4; i += stride) {
        float4 o = out[i];
        float4 v;
        v.x = 1.0f / (1.0f + expf(-o.x));
        v.y = 1.0f / (1.0f + expf(-o.y));
        v.z = 1.0f / (1.0f + expf(-o.z));
        v.w = 1.0f / (1.0f + expf(-o.w));
        H4 hv; hv.lo = __floats2half2_rn(v.x, v.y); hv.hi = __floats2half2_rn(v.z, v.w);
        ga[i] = hv;
        float4 t = tgt[i];
        H4 ht; ht.lo = __floats2half2_rn(t.x, t.y); ht.hi = __floats2half2_rn(t.z, t.w);
        gb[i] = ht;
    }
}

// ---------------------------------------------------------------------------
// Fused TWO skeleton iterations, 2 ROWS PER STEP (12 double-steps).
// At double-step with loaded rows (ya, ya+1):
//   E1 rows ya-1, ya     (shared vertical mid)
//   F  rows ya-2, ya-1   (= E2, new img)
//   H  rows ya-2, ya-1   (masked hmax of F)
//   E3 rows ya-3, ya-2
//   B  rows ya-3, ya-2   (masked hmax of E3)
//   delta1 rows ya-3, ya-2 (latter saved to dprev)
//   delta2 rows ya-4, ya-3
//   outputs rows ya-4, ya-3: skel + both deltas; img = F rows (pre-shift f1,f2)
// FIRST additionally produces skel0 = relu(I - dilate(E1)) via H0 rows ya-1, ya
// and a one-double-step delay chain (skd1, skd2), replacing the skel load.
// All min/max reassociations are exact (selection ops) -> bitwise identical.
// ---------------------------------------------------------------------------
template<bool RIN, bool CIN, bool FIRST>
__device__ __forceinline__ void it2_core(
    const __half* __restrict__ src, __half* __restrict__ dst,
    __half* __restrict__ skel, const int lane, const int c0, const int r0)
{
    const bool colok = CIN || ((c0 >= 0) && (c0 < WW));
    const bool stok = (lane >= 1) && (lane <= 30) && (CIN || (c0 < WW));

    int y0 = r0 - 4;
    const __half* srcp = src + y0 * WW + c0;
    __half* const skb = skel + c0;
    __half* const dsb = dst + c0;

    // initial prefetch of rows y0, y0+1 (+ their edges)
    H4 pf1, pf2;
    __half p1l, p1r, p2l, p2r;
    {
        bool ok1 = colok && (RIN || (unsigned)y0 < (unsigned)HH);
        bool ok2 = colok && (RIN || (unsigned)(y0 + 1) < (unsigned)HH);
        pf1 = ok1 ? *(const H4*)srcp : h4_inf();
        pf2 = ok2 ? *(const H4*)(srcp + WW) : h4_inf();
        srcp += 2 * WW;
        edges_of(pf1, p1l, p1r);
        edges_of(pf2, p2l, p2r);
    }

    H4 i1 = h4_inf(), i2 = h4_inf();            // I[ya-2], I[ya-1]
    __half i2l = h_inf(), i2r = h_inf();        // edges of I[ya-1]
    H4 e1 = h4_inf(), e2 = h4_inf();            // E1[ya-3], E1[ya-2]
    __half e2l = h_inf(), e2r = h_inf();        // edges of E1[ya-2]
    H4 f1 = h4_inf(), f2 = h4_inf();            // F[ya-4], F[ya-3]
    __half f2l = h_inf(), f2r = h_inf();        // edges of F[ya-3]
    H4 h1 = h4_ninf(), h2 = h4_ninf();          // H[ya-4], H[ya-3]
    H4 b1 = h4_ninf(), b2 = h4_ninf();          // B[ya-5], B[ya-4]
    H4 dprev = h4_zero();                       // delta1[ya-4]
    H4 sp1 = h4_zero(), sp2 = h4_zero();        // skel[ya-4], skel[ya-3]
    H4 g1 = h4_ninf(), g2 = h4_ninf();          // H0[ya-3], H0[ya-2]   (FIRST)
    H4 skd1 = h4_zero(), skd2 = h4_zero();      // skel0[ya-4], [ya-3]  (FIRST)

#pragma unroll 1
    for (int ds = 0; ds < 12; ++ds) {
        const int ya = y0;
        H4 ic = pf1, id = pf2;                  // I[ya], I[ya+1]
        const __half icl = p1l, icr = p1r, idl = p2l, idr = p2r;
        // prefetch rows ya+2, ya+3 (+ edges, off the critical path)
        {
            bool ok1 = colok && (RIN || (unsigned)(ya + 2) < (unsigned)HH);
            bool ok2 = colok && (RIN || (unsigned)(ya + 3) < (unsigned)HH);
            pf1 = ok1 ? *(const H4*)srcp : h4_inf();
            pf2 = ok2 ? *(const H4*)(srcp + WW) : h4_inf();
            srcp += 2 * WW;
            edges_of(pf1, p1l, p1r);
            edges_of(pf2, p2l, p2r);
        }
        // E1 rows ya-1, ya (shared vertical mid)
        H4 midI = min_h(i2, ic);
        H4 E1a = min_h(min_h(midI, i1), comb_minh(i2, i2l, i2r, lane));
        H4 E1b = min_h(min_h(midI, id), comb_minh(ic, icl, icr, lane));
        __half eal, ear, ebl, ebr;
        edges_of(E1a, eal, ear);
        edges_of(E1b, ebl, ebr);
        // FIRST: H0 rows ya-1, ya = hmax(masked E1)
        H4 H0a, H0b;
        if (FIRST) {
            if (RIN && CIN) {
                H0a = comb_maxh(E1a, eal, ear, lane);
                H0b = comb_maxh(E1b, ebl, ebr, lane);
            } else {
                bool oka = colok && (RIN || (unsigned)(ya - 1) < (unsigned)HH);
                bool okb = colok && (RIN || (unsigned)(ya) < (unsigned)HH);
                H0a = hmax3h(selneg(E1a, oka), lane);
                H0b = hmax3h(selneg(E1b, okb), lane);
            }
        }
        // F rows ya-2, ya-1
        H4 midE = min_h(e2, E1a);
        H4 Fa = min_h(min_h(midE, e1), comb_minh(e2, e2l, e2r, lane));
        H4 Fb = min_h(min_h(midE, E1b), comb_minh(E1a, eal, ear, lane));
        __half fal, far_, fbl, fbr;
        edges_of(Fa, fal, far_);
        edges_of(Fb, fbl, fbr);
        // H rows ya-2, ya-1 (masked hmax of F)
        H4 Ha, Hb;
        if (RIN && CIN) {
            Ha = comb_maxh(Fa, fal, far_, lane);
            Hb = comb_maxh(Fb, fbl, fbr, lane);
        } else {
            bool oka = colok && (RIN || (unsigned)(ya - 2) < (unsigned)HH);
            bool okb = colok && (RIN || (unsigned)(ya - 1) < (unsigned)HH);
            Ha = hmax3h(selneg(Fa, oka), lane);
            Hb = hmax3h(selneg(Fb, okb), lane);
        }
        // E3 rows ya-3, ya-2
        H4 midF = min_h(f2, Fa);
        H4 E3a = min_h(min_h(midF, f1), comb_minh(f2, f2l, f2r, lane));
        H4 E3b = min_h(min_h(midF, Fb), comb_minh(Fa, fal, far_, lane));
        // B rows ya-3, ya-2 (masked hmax of E3, same-step shuffles)
        H4 Ba, Bb;
        if (RIN && CIN) {
            Ba = hmax3h(E3a, lane);
            Bb = hmax3h(E3b, lane);
        } else {
            bool oka = colok && (RIN || (unsigned)(ya - 3) < (unsigned)HH);
            bool okb = colok && (RIN || (unsigned)(ya - 2) < (unsigned)HH);
            Ba = hmax3h(selneg(E3a, oka), lane);
            Bb = hmax3h(selneg(E3b, okb), lane);
        }
        // delta1 rows ya-3, ya-2 (E1[ya-3]=e1, E1[ya-2]=e2, pre-shift)
        H4 mH = max_h(h2, Ha);
        H4 d1a = relu_subh(e1, max_h(mH, h1));
        H4 d1b = relu_subh(e2, max_h(mH, Hb));
        // delta2 rows ya-4, ya-3 (F[ya-4]=f1, F[ya-3]=f2, pre-shift)
        H4 mB = max_h(b2, Ba);
        H4 d2a = relu_subh(f1, max_h(mB, b1));
        H4 d2b = relu_subh(f2, max_h(mB, Bb));
        // outputs rows ya-4, ya-3
        if (ya - 4 >= r0) {
            if (stok) {
                H4 s1 = FIRST ? skd1 : sp1;
                H4 s2 = FIRST ? skd2 : sp2;
                skel_updh(s1, dprev);
                skel_updh(s1, d2a);
                skel_updh(s2, d1a);
                skel_updh(s2, d2b);
                *(H4*)(skb + (ya - 4) * WW) = s1;
                *(H4*)(skb + (ya - 3) * WW) = s2;
                *(H4*)(dsb + (ya - 4) * WW) = f1;
                *(H4*)(dsb + (ya - 3) * WW) = f2;
            }
        }
        dprev = d1b;
        // skel prefetch rows ya-2, ya-1 (next step's outputs)
        if (!FIRST) {
            if (stok && (RIN || (unsigned)(ya - 2) < (unsigned)HH))
                sp1 = *(const H4*)(skb + (ya - 2) * WW);
            if (stok && (RIN || (unsigned)(ya - 1) < (unsigned)HH))
                sp2 = *(const H4*)(skb + (ya - 1) * WW);
        }
        // FIRST: skel0 rows ya-2, ya-1 via D0 from H0 (I pre-shift)
        if (FIRST) {
            H4 mG = max_h(g2, H0a);
            skd1 = relu_subh(i1, max_h(mG, g1));
            skd2 = relu_subh(i2, max_h(mG, H0b));
            g1 = H0a; g2 = H0b;
        }
        // state shifts
        i1 = ic; i2 = id; i2l = idl; i2r = idr;
        e1 = E1a; e2 = E1b; e2l = ebl; e2r = ebr;
        f1 = Fa;  f2 = Fb;  f2l = fbl; f2r = fbr;
        h1 = Ha;  h2 = Hb;
        b1 = Ba;  b2 = Bb;
        y0 += 2;
    }
}

__global__ void __launch_bounds__(IT2_BLOCK, 5) k_iter2(int flip) {
    const int lane = threadIdx.x & 31;
    const int gw = (blockIdx.x * IT2_BLOCK + threadIdx.x) >> 5;
    const int strip = gw % STRIPS;
    const int t = gw / STRIPS;
    const int chunk = t & (CHUNKS - 1);
    const int z = t / CHUNKS;

    const __half* __restrict__ src = (flip ? g_imgB : g_imgA) + z * HWSZ;
    __half* __restrict__ dst = (flip ? g_imgA : g_imgB) + z * HWSZ;
    __half* __restrict__ skel = g_skel + z * HWSZ;

    const int c0 = strip * 120 - 4 + 4 * lane;
    const int r0 = chunk * CHUNK_ROWS;

    const bool rin = (chunk >= 1) && (chunk <= 30);
    const bool cin = (strip >= 1) && (strip <= 3);
    if (rin) {
        if (cin) it2_core<true, true, false>(src, dst, skel, lane, c0, r0);
        else     it2_core<true, false, false>(src, dst, skel, lane, c0, r0);
    } else {
        if (cin) it2_core<false, true, false>(src, dst, skel, lane, c0, r0);
        else     it2_core<false, false, false>(src, dst, skel, lane, c0, r0);
    }
}

// First launch: open-init (skel0) + iterations 1,2 fused. imgA -> imgB.
__global__ void __launch_bounds__(IT2_BLOCK, 5) k_first() {
    const int lane = threadIdx.x & 31;
    const int gw = (blockIdx.x * IT2_BLOCK + threadIdx.x) >> 5;
    const int strip = gw % STRIPS;
    const int t = gw / STRIPS;
    const int chunk = t & (CHUNKS - 1);
    const int z = t / CHUNKS;

    const __half* __restrict__ src = g_imgA + z * HWSZ;
    __half* __restrict__ dst = g_imgB + z * HWSZ;
    __half* __restrict__ skel = g_skel + z * HWSZ;

    const int c0 = strip * 120 - 4 + 4 * lane;
    const int r0 = chunk * CHUNK_ROWS;

    const bool rin = (chunk >= 1) && (chunk <= 30);
    const bool cin = (strip >= 1) && (strip <= 3);
    if (rin) {
        if (cin) it2_core<true, true, true>(src, dst, skel, lane, c0, r0);
        else     it2_core<true, false, true>(src, dst, skel, lane, c0, r0);
    } else {
        if (cin) it2_core<false, true, true>(src, dst, skel, lane, c0, r0);
        else     it2_core<false, false, true>(src, dst, skel, lane, c0, r0);
    }
}

// ---------------------------------------------------------------------------
// Reductions (sigmoid recomputed inline from output; bitwise-same as before)
// ---------------------------------------------------------------------------
__global__ void k_zero() {
    int t = threadIdx.x;
    if (t < NIMG * 7) ((double*)g_sums)[t] = 0.0;
}

__global__ void k_reduce(const float* __restrict__ outp, const float* __restrict__ tgt) {
    const int n = blockIdx.y;
    const H4* __restrict__ sp = (const H4*)(g_skel + n * HWSZ);
    const H4* __restrict__ sl = (const H4*)(g_skel + (NIMG + n) * HWSZ);
    const float4* __restrict__ oo = (const float4*)(outp + n * HWSZ);
    const float4* __restrict__ tt = (const float4*)(tgt + n * HWSZ);
    const int n4 = HWSZ / 4;

    double a0 = 0, a1 = 0, a2 = 0, a3 = 0, a4 = 0, a5 = 0, a6 = 0;
    for (int i = blockIdx.x * blockDim.x + threadIdx.x; i < n4;
         i += gridDim.x * blockDim.x) {
        H4 s1h = sp[i], s2h = sl[i];
        float2 s1lo = __half22float2(s1h.lo), s1hi = __half22float2(s1h.hi);
        float2 s2lo = __half22float2(s2h.lo), s2hi = __half22float2(s2h.hi);
        float4 o = oo[i], tv = tt[i];
        float4 pv;
        pv.x = 1.0f / (1.0f + expf(-o.x));
        pv.y = 1.0f / (1.0f + expf(-o.y));
        pv.z = 1.0f / (1.0f + expf(-o.z));
        pv.w = 1.0f / (1.0f + expf(-o.w));
        a0 += (double)(s1lo.x * tv.x + s1lo.y * tv.y + s1hi.x * tv.z + s1hi.y * tv.w);
        a1 += (double)(s1lo.x + s1lo.y + s1hi.x + s1hi.y);
        a2 += (double)(s2lo.x * pv.x + s2lo.y * pv.y + s2hi.x * pv.z + s2hi.y * pv.w);
        a3 += (double)(s2lo.x + s2lo.y + s2hi.x + s2hi.y);
        a4 += (double)(pv.x * tv.x + pv.y * tv.y + pv.z * tv.z + pv.w * tv.w);
        a5 += (double)(pv.x + pv.y + pv.z + pv.w);
        a6 += (double)(tv.x + tv.y + tv.z + tv.w);
    }
#pragma unroll
    for (int o = 16; o > 0; o >>= 1) {
        a0 += __shfl_down_sync(0xffffffffu, a0, o);
        a1 += __shfl_down_sync(0xffffffffu, a1, o);
        a2 += __shfl_down_sync(0xffffffffu, a2, o);
        a3 += __shfl_down_sync(0xffffffffu, a3, o);
        a4 += __shfl_down_sync(0xffffffffu, a4, o);
        a5 += __shfl_down_sync(0xffffffffu, a5, o);
        a6 += __shfl_down_sync(0xffffffffu, a6, o);
    }
    if ((threadIdx.x & 31) == 0) {
        atomicAdd(&g_sums[n][0], a0);
        atomicAdd(&g_sums[n][1], a1);
        atomicAdd(&g_sums[n][2], a2);
        atomicAdd(&g_sums[n][3], a3);
        atomicAdd(&g_sums[n][4], a4);
        atomicAdd(&g_sums[n][5], a5);
        atomicAdd(&g_sums[n][6], a6);
    }
}

__global__ void k_final(float* __restrict__ out, int out_size) {
    if (threadIdx.x == 0 && blockIdx.x == 0) {
        const double smooth = 1.0;
        double cl = 0.0, dice = 0.0;
        for (int n = 0; n < NIMG; n++) {
            double A = g_sums[n][0], B = g_sums[n][1], C = g_sums[n][2],
                   D = g_sums[n][3], E = g_sums[n][4], F = g_sums[n][5],
                   G = g_sums[n][6];
            double tprec = (A + smooth) / (B + smooth);
            double tsens = (C + smooth) / (D + smooth);
            cl += 1.0 - 2.0 * tprec * tsens / (tprec + tsens);
            dice += 1.0 - 2.0 * (E + smooth) / (F + G + smooth);
        }
        cl /= NIMG;
        dice /= NIMG;
        float loss = (float)(0.7 * dice + 0.3 * cl);
        for (int i = 0; i < out_size; i++) out[i] = loss;
    }
}

// ---------------------------------------------------------------------------
extern "C" void kernel_launch(void* const* d_in, const int* in_sizes, int n_in,
                              void* d_out, int out_size) {
    const float* output = (const float*)d_in[0];
    const float* target = (const float*)d_in[1];
    float* out = (float*)d_out;

    k_init<<<1024, 256>>>((const float4*)output, (const float4*)target);

    // iterations 1-2 fused with open-init (imgA -> imgB)
    k_first<<<IT2_GRID, IT2_BLOCK>>>();

    // iterations 3..50 = 24 fused-2 launches, alternating B->A / A->B
    for (int j = 1; j < NITER / 2; ++j) {
        k_iter2<<<IT2_GRID, IT2_BLOCK>>>(j & 1);
    }

    k_zero<<<1, 64>>>();
    k_reduce<<<dim3(32, NIMG), 256>>>(output, target);
    k_final<<<1, 32>>>(out, out_size);
}